// round 5
// baseline (speedup 1.0000x reference)
#include <cuda_runtime.h>
#include <cuda_bf16.h>
#include <cstdint>

#define NN 50000
#define EMAX 800000
#define ETOT (EMAX + NN)
#define IN_CH 128
#define HID 64
#define HEADS 4
#define D1 (HEADS * HID)   // 256
#define NBLK 49            // ceil(NN/1024)
#define KP1 (3 * IN_CH)    // 384  3-term split-bf16 K for GEMM1
#define KP2 (3 * D1)       // 768  3-term split-bf16 K for GEMM2

// ---------------- scratch (static device globals; no runtime alloc) --------
__device__ __align__(128) float g_h1[NN * D1];
__device__ __align__(128) float g_h2[NN * HID];
__device__ __align__(128) float g_buf2[NN * HID];
__device__ __align__(128) __nv_bfloat16 g_A1[(size_t)NN * KP1];
__device__ __align__(128) __nv_bfloat16 g_A2[(size_t)NN * KP2];
__device__ __align__(128) __nv_bfloat16 g_W1p[(size_t)KP1 * D1];
__device__ __align__(128) __nv_bfloat16 g_W2p[(size_t)KP2 * HID];
__device__ __align__(128) float g_asrc1[NN * HEADS];
__device__ __align__(128) float g_adst1[NN * HEADS];
__device__ __align__(128) float g_asrc2[NN];
__device__ __align__(128) float g_adst2[NN];
__device__ __align__(128) float g_esc[(size_t)HEADS * ETOT];
__device__ __align__(128) int   g_deg[NN];
__device__ __align__(128) int   g_rowptr[NN + 1];
__device__ __align__(128) int   g_cursor[NN];
__device__ __align__(128) int   g_esrc[ETOT];
__device__ __align__(128) int   g_part[64];

// ---------------- CSR build -------------------------------------------------
__global__ void k_zero_deg() {
    int i = blockIdx.x * blockDim.x + threadIdx.x;
    if (i < NN) g_deg[i] = 0;
}

__global__ void k_count(const int* __restrict__ dst, int E) {
    int i = blockIdx.x * blockDim.x + threadIdx.x;
    if (i < E) atomicAdd(&g_deg[dst[i]], 1);
}

__global__ void k_scan1() {
    __shared__ int ws[32];
    int t = threadIdx.x;
    int i = blockIdx.x * 1024 + t;
    int v = (i < NN) ? (g_deg[i] + 1) : 0;
    int x = v;
    #pragma unroll
    for (int o = 1; o < 32; o <<= 1) {
        int y = __shfl_up_sync(0xFFFFFFFF, x, o);
        if ((t & 31) >= o) x += y;
    }
    if ((t & 31) == 31) ws[t >> 5] = x;
    __syncthreads();
    if (t < 32) {
        int s = ws[t];
        #pragma unroll
        for (int o = 1; o < 32; o <<= 1) {
            int y = __shfl_up_sync(0xFFFFFFFF, s, o);
            if (t >= o) s += y;
        }
        ws[t] = s;
    }
    __syncthreads();
    int incl = x + ((t >= 32) ? ws[(t >> 5) - 1] : 0);
    if (i < NN) g_rowptr[i + 1] = incl;
    if (t == 1023) g_part[blockIdx.x] = incl;
}

__global__ void k_scan2() {
    int l = threadIdx.x;
    int a = (l < NBLK) ? g_part[l] : 0;
    int b = (l + 32 < NBLK) ? g_part[l + 32] : 0;
    int ia = a;
    #pragma unroll
    for (int o = 1; o < 32; o <<= 1) {
        int y = __shfl_up_sync(0xFFFFFFFF, ia, o);
        if (l >= o) ia += y;
    }
    int tot = __shfl_sync(0xFFFFFFFF, ia, 31);
    int ib = b;
    #pragma unroll
    for (int o = 1; o < 32; o <<= 1) {
        int y = __shfl_up_sync(0xFFFFFFFF, ib, o);
        if (l >= o) ib += y;
    }
    g_part[l] = ia - a;
    g_part[l + 32] = tot + ib - b;
}

__global__ void k_scan3() {
    int i = blockIdx.x * blockDim.x + threadIdx.x;
    if (i >= NN) return;
    int off = g_part[i >> 10];
    int rp = g_rowptr[i + 1] + off;
    g_rowptr[i + 1] = rp;
    g_cursor[i] = rp - (g_deg[i] + 1);
    if (i == 0) g_rowptr[0] = 0;
}

__global__ void k_scatter(const int* __restrict__ src, const int* __restrict__ dst, int E) {
    int i = blockIdx.x * blockDim.x + threadIdx.x;
    if (i < E) {
        int p = atomicAdd(&g_cursor[dst[i]], 1);
        g_esrc[p] = src[i];
    } else if (i < E + NN) {
        int n = i - E;
        int p = atomicAdd(&g_cursor[n], 1);
        g_esrc[p] = n;
    }
}

// ---------------- 3-term split-bf16 packing ---------------------------------
// product (hiA+loA)(hiB+loB) ~= hiA*hiB + hiA*loB + loA*hiB  (drop lo*lo)
// A pattern per k: [hi, hi, lo]  B pattern per k: [hi, lo, hi]
__device__ __forceinline__ void split_bf16(float f, __nv_bfloat16& hi, __nv_bfloat16& lo) {
    hi = __float2bfloat16(f);
    lo = __float2bfloat16(f - __bfloat162float(hi));
}

__global__ void k_packA1(const float* __restrict__ x) {
    int i = blockIdx.x * blockDim.x + threadIdx.x;
    if (i >= NN * KP1) return;
    int m = i / KP1, p = i - m * KP1;
    int k = p / 3, r = p - 3 * k;
    __nv_bfloat16 hi, lo;
    split_bf16(x[m * IN_CH + k], hi, lo);
    g_A1[i] = (r == 2) ? lo : hi;
}

__global__ void k_packW(const float* __restrict__ W, __nv_bfloat16* __restrict__ dst,
                        int K, int N) {
    int i = blockIdx.x * blockDim.x + threadIdx.x;
    if (i >= 3 * K * N) return;
    int kp = i / N, n = i - kp * N;
    int k = kp / 3, r = kp - 3 * k;
    __nv_bfloat16 hi, lo;
    split_bf16(W[k * N + n], hi, lo);
    dst[i] = (r == 1) ? lo : hi;
}

// ---------------- bf16 tensor-core GEMM ------------------------------------
// BM=128, BK=64, warp tile 64x32, WM x WN warps, bf16 in / fp32 out
__device__ __forceinline__ void cp16(uint32_t dst, const void* src, int sz) {
    asm volatile("cp.async.ca.shared.global [%0], [%1], 16, %2;\n"
                 :: "r"(dst), "l"(src), "r"(sz));
}
__device__ __forceinline__ void ldsm4(uint32_t* r, uint32_t a) {
    asm volatile("ldmatrix.sync.aligned.m8n8.x4.shared.b16 {%0,%1,%2,%3}, [%4];"
                 : "=r"(r[0]), "=r"(r[1]), "=r"(r[2]), "=r"(r[3]) : "r"(a));
}
__device__ __forceinline__ void ldsm4t(uint32_t* r, uint32_t a) {
    asm volatile("ldmatrix.sync.aligned.m8n8.x4.trans.shared.b16 {%0,%1,%2,%3}, [%4];"
                 : "=r"(r[0]), "=r"(r[1]), "=r"(r[2]), "=r"(r[3]) : "r"(a));
}
__device__ __forceinline__ void mma16816(float* c, const uint32_t* a, uint32_t b0, uint32_t b1) {
    asm volatile("mma.sync.aligned.m16n8k16.row.col.f32.bf16.bf16.f32 "
                 "{%0,%1,%2,%3}, {%4,%5,%6,%7}, {%8,%9}, {%0,%1,%2,%3};"
                 : "+f"(c[0]), "+f"(c[1]), "+f"(c[2]), "+f"(c[3])
                 : "r"(a[0]), "r"(a[1]), "r"(a[2]), "r"(a[3]), "r"(b0), "r"(b1));
}
__device__ __forceinline__ uint32_t sw128(uint32_t off) {
    return off ^ ((off >> 3) & 0x70);
}

template<int BN, int WM, int WN>
__global__ __launch_bounds__(WM * WN * 32) void k_gemm_bf16(
        const __nv_bfloat16* __restrict__ A, const __nv_bfloat16* __restrict__ B,
        float* __restrict__ C, int M, int N, int Kp) {
    constexpr int THREADS = WM * WN * 32;
    constexpr int ASTG = 128 * 128;      // 16KB per stage (128 rows x 128B)
    constexpr int BSTG = 64 * BN * 2;    // 64 rows x BN bf16
    extern __shared__ __align__(1024) char smem_raw[];
    uint32_t sA = (uint32_t)__cvta_generic_to_shared(smem_raw);
    uint32_t sB = sA + 2 * ASTG;
    int t = threadIdx.x;
    int warp = t >> 5, lane = t & 31;
    int wm = warp & (WM - 1), wn = warp / WM;
    int row0 = blockIdx.y * 128, col0 = blockIdx.x * BN;

    float acc[4][4][4];
    #pragma unroll
    for (int mt = 0; mt < 4; mt++)
        #pragma unroll
        for (int nt = 0; nt < 4; nt++)
            #pragma unroll
            for (int r = 0; r < 4; r++) acc[mt][nt][r] = 0.f;

    int nIter = Kp >> 6;

    auto load_tiles = [&](int it, int buf) {
        int k0 = it << 6;
        #pragma unroll
        for (int i = 0; i < 1024 / THREADS; i++) {   // A: 128 rows x 8 x 16B
            int id = t + i * THREADS;
            int r = id >> 3, kc = id & 7;
            uint32_t off = sw128(r * 128 + kc * 16);
            int sz = (row0 + r < M) ? 16 : 0;
            cp16(sA + buf * ASTG + off, A + (size_t)(row0 + r) * Kp + k0 + kc * 8, sz);
        }
        #pragma unroll
        for (int i = 0; i < (64 * BN / 8) / THREADS; i++) {  // B: 64 rows x BN/8 x 16B
            int id = t + i * THREADS;
            int r = id / (BN / 8), c = id % (BN / 8);
            int n0 = c * 8;
            uint32_t off = (uint32_t)(n0 >> 6) * 8192 + sw128(r * 128 + (n0 & 63) * 2);
            cp16(sB + buf * BSTG + off, B + (size_t)(k0 + r) * N + col0 + n0, 16);
        }
        asm volatile("cp.async.commit_group;\n" ::: "memory");
    };

    load_tiles(0, 0);
    for (int it = 0; it < nIter; it++) {
        int buf = it & 1;
        if (it + 1 < nIter) {
            load_tiles(it + 1, buf ^ 1);
            asm volatile("cp.async.wait_group 1;\n" ::: "memory");
        } else {
            asm volatile("cp.async.wait_group 0;\n" ::: "memory");
        }
        __syncthreads();
        uint32_t aBuf = sA + buf * ASTG;
        uint32_t bBuf = sB + buf * BSTG;
        #pragma unroll
        for (int kk = 0; kk < 4; kk++) {
            int k0 = kk << 4;
            uint32_t afr[4][4], bfr[2][4];
            #pragma unroll
            for (int mt = 0; mt < 4; mt++) {
                int r = wm * 64 + mt * 16 + (lane & 15);
                uint32_t off = sw128(r * 128 + (k0 + (lane >> 4) * 8) * 2);
                ldsm4(afr[mt], aBuf + off);
            }
            #pragma unroll
            for (int np = 0; np < 2; np++) {
                int k = k0 + (lane & 7) + ((lane >> 3) & 1) * 8;
                int n = wn * 32 + np * 16 + (lane >> 4) * 8;
                uint32_t off = (uint32_t)(n >> 6) * 8192 + sw128(k * 128 + (n & 63) * 2);
                ldsm4t(bfr[np], bBuf + off);
            }
            #pragma unroll
            for (int mt = 0; mt < 4; mt++)
                #pragma unroll
                for (int nt = 0; nt < 4; nt++)
                    mma16816(acc[mt][nt], afr[mt],
                             bfr[nt >> 1][(nt & 1) * 2], bfr[nt >> 1][(nt & 1) * 2 + 1]);
        }
        __syncthreads();
    }

    #pragma unroll
    for (int mt = 0; mt < 4; mt++)
        #pragma unroll
        for (int nt = 0; nt < 4; nt++) {
            int r = row0 + wm * 64 + mt * 16 + (lane >> 2);
            int cn = col0 + wn * 32 + nt * 8 + (lane & 3) * 2;
            if (r < M) {
                C[(size_t)r * N + cn]     = acc[mt][nt][0];
                C[(size_t)r * N + cn + 1] = acc[mt][nt][1];
            }
            if (r + 8 < M) {
                C[(size_t)(r + 8) * N + cn]     = acc[mt][nt][2];
                C[(size_t)(r + 8) * N + cn + 1] = acc[mt][nt][3];
            }
        }
}

// ---------------- attention scores -----------------------------------------
__global__ void k_scores1(const float* __restrict__ att_src, const float* __restrict__ att_dst) {
    int n = blockIdx.x;
    int t = threadIdx.x;
    int h = t >> 5, lane = t & 31;
    const float* hp = g_h1 + (size_t)n * D1 + h * HID;
    float s1 = hp[lane] * att_src[h * HID + lane] + hp[lane + 32] * att_src[h * HID + lane + 32];
    float s2 = hp[lane] * att_dst[h * HID + lane] + hp[lane + 32] * att_dst[h * HID + lane + 32];
    #pragma unroll
    for (int o = 16; o; o >>= 1) {
        s1 += __shfl_down_sync(0xFFFFFFFF, s1, o);
        s2 += __shfl_down_sync(0xFFFFFFFF, s2, o);
    }
    if (lane == 0) {
        g_asrc1[n * HEADS + h] = s1;
        g_adst1[n * HEADS + h] = s2;
    }
}

__global__ void k_scores2(const float* __restrict__ att_src, const float* __restrict__ att_dst) {
    int w = threadIdx.x >> 5, lane = threadIdx.x & 31;
    int n = blockIdx.x * 8 + w;
    if (n >= NN) return;
    const float* hp = g_h2 + (size_t)n * HID;
    float s1 = hp[lane] * att_src[lane] + hp[lane + 32] * att_src[lane + 32];
    float s2 = hp[lane] * att_dst[lane] + hp[lane + 32] * att_dst[lane + 32];
    #pragma unroll
    for (int o = 16; o; o >>= 1) {
        s1 += __shfl_down_sync(0xFFFFFFFF, s1, o);
        s2 += __shfl_down_sync(0xFFFFFFFF, s2, o);
    }
    if (lane == 0) {
        g_asrc2[n] = s1;
        g_adst2[n] = s2;
    }
}

// ---------------- aggregation ----------------------------------------------
__device__ __forceinline__ float lrelu(float x) { return x > 0.f ? x : 0.2f * x; }

// layer 1: one node per 128-thread block; warp h = head h; epilogue packs A2
__global__ void k_agg1(const float* __restrict__ bias) {
    int n = blockIdx.x;
    int t = threadIdx.x;
    int h = t >> 5, lane = t & 31;
    int beg = g_rowptr[n], end = g_rowptr[n + 1];
    float ad = g_adst1[n * HEADS + h];
    float* esc = g_esc + (size_t)h * ETOT;

    float m = -1e30f, d = 0.f;
    for (int e = beg + lane; e < end; e += 32) {
        int s = g_esrc[e];
        float x = lrelu(g_asrc1[s * HEADS + h] + ad);
        esc[e] = x;
        float mn = fmaxf(m, x);
        d = d * __expf(m - mn) + __expf(x - mn);
        m = mn;
    }
    #pragma unroll
    for (int o = 16; o; o >>= 1) {
        float mo = __shfl_xor_sync(0xFFFFFFFF, m, o);
        float dd = __shfl_xor_sync(0xFFFFFFFF, d, o);
        float mn = fmaxf(m, mo);
        d = d * __expf(m - mn) + dd * __expf(mo - mn);
        m = mn;
    }
    float inv = 1.f / (d + 1e-16f);
    __syncwarp();

    float2 acc = make_float2(0.f, 0.f);
    int c = lane << 1;
    const float* hrow = g_h1 + h * HID + c;
    for (int e0 = beg; e0 < end; e0 += 32) {
        int e = e0 + lane;
        int s = 0; float w = 0.f;
        if (e < end) {
            s = g_esrc[e];
            w = __expf(esc[e] - m) * inv;
        }
        int cnt = min(32, end - e0);
        for (int j = 0; j < cnt; j++) {
            int   sj = __shfl_sync(0xFFFFFFFF, s, j);
            float wj = __shfl_sync(0xFFFFFFFF, w, j);
            float2 v = *reinterpret_cast<const float2*>(hrow + (size_t)sj * D1);
            acc.x += v.x * wj;
            acc.y += v.y * wj;
        }
    }
    int j0 = h * HID + c;
    float v0 = acc.x + bias[j0];
    float v1 = acc.y + bias[j0 + 1];
    v0 = v0 > 0.f ? v0 : __expf(v0) - 1.f;   // elu
    v1 = v1 > 0.f ? v1 : __expf(v1) - 1.f;
    __nv_bfloat16 h0, l0, h1, l1;
    split_bf16(v0, h0, l0);
    split_bf16(v1, h1, l1);
    // pattern per element: [hi, hi, lo]; 2 elements -> 6 bf16 at 3*j0
    __nv_bfloat162* p = reinterpret_cast<__nv_bfloat162*>(g_A2 + (size_t)n * KP2 + 3 * j0);
    p[0] = __halves2bfloat162(h0, h0);
    p[1] = __halves2bfloat162(l0, h1);
    p[2] = __halves2bfloat162(h1, l1);
}

// layer 2: one node per warp
__global__ void k_agg2(const float* __restrict__ bias) {
    int w = threadIdx.x >> 5, lane = threadIdx.x & 31;
    int n = blockIdx.x * 4 + w;
    if (n >= NN) return;
    int beg = g_rowptr[n], end = g_rowptr[n + 1];
    float ad = g_adst2[n];

    float m = -1e30f, d = 0.f;
    for (int e = beg + lane; e < end; e += 32) {
        int s = g_esrc[e];
        float x = lrelu(g_asrc2[s] + ad);
        g_esc[e] = x;
        float mn = fmaxf(m, x);
        d = d * __expf(m - mn) + __expf(x - mn);
        m = mn;
    }
    #pragma unroll
    for (int o = 16; o; o >>= 1) {
        float mo = __shfl_xor_sync(0xFFFFFFFF, m, o);
        float dd = __shfl_xor_sync(0xFFFFFFFF, d, o);
        float mn = fmaxf(m, mo);
        d = d * __expf(m - mn) + dd * __expf(mo - mn);
        m = mn;
    }
    float inv = 1.f / (d + 1e-16f);
    __syncwarp();

    float2 acc = make_float2(0.f, 0.f);
    int c = lane << 1;
    for (int e0 = beg; e0 < end; e0 += 32) {
        int e = e0 + lane;
        int s = 0; float wt = 0.f;
        if (e < end) {
            s = g_esrc[e];
            wt = __expf(g_esc[e] - m) * inv;
        }
        int cnt = min(32, end - e0);
        for (int j = 0; j < cnt; j++) {
            int   sj = __shfl_sync(0xFFFFFFFF, s, j);
            float wj = __shfl_sync(0xFFFFFFFF, wt, j);
            float2 v = *reinterpret_cast<const float2*>(g_h2 + (size_t)sj * HID + c);
            acc.x += v.x * wj;
            acc.y += v.y * wj;
        }
    }
    float v0 = acc.x + bias[c];
    float v1 = acc.y + bias[c + 1];
    g_buf2[(size_t)n * HID + c]     = v0 > 0.f ? v0 : __expf(v0) - 1.f;
    g_buf2[(size_t)n * HID + c + 1] = v1 > 0.f ? v1 : __expf(v1) - 1.f;
}

// ---------------- fused MLP head -------------------------------------------
__global__ void k_mlp(const float* __restrict__ Wm1, const float* __restrict__ bm1,
                      const float* __restrict__ Wm2, const float* __restrict__ bm2,
                      float* __restrict__ out) {
    __shared__ float sW1[HID * 32];
    __shared__ float sW2[32 * 2];
    __shared__ float sb1[32], sb2[2];
    __shared__ float hm[8][33];
    int t = threadIdx.x;
    for (int i = t; i < HID * 32; i += 256) sW1[i] = Wm1[i];
    if (t < 64) sW2[t] = Wm2[t];
    if (t < 32) sb1[t] = bm1[t];
    if (t < 2)  sb2[t] = bm2[t];
    __syncthreads();
    int nl = t >> 5, j = t & 31;
    int node = blockIdx.x * 8 + nl;
    if (node < NN) {
        const float* hrow = g_buf2 + (size_t)node * HID;
        float acc = sb1[j];
        #pragma unroll
        for (int k = 0; k < HID; k++) acc += hrow[k] * sW1[k * 32 + j];
        hm[nl][j] = fmaxf(acc, 0.f);
    }
    __syncthreads();
    if (node < NN && j < 2) {
        float acc = sb2[j];
        #pragma unroll
        for (int k = 0; k < 32; k++) acc += hm[nl][k] * sW2[k * 2 + j];
        out[node * 2 + j] = acc;
    }
}

// ---------------- launch ----------------------------------------------------
extern "C" void kernel_launch(void* const* d_in, const int* in_sizes, int n_in,
                              void* d_out, int out_size) {
    const float* x        = (const float*)d_in[0];
    const int*   eidx     = (const int*)d_in[1];
    const float* W1       = (const float*)d_in[2];
    const float* att_src1 = (const float*)d_in[3];
    const float* att_dst1 = (const float*)d_in[4];
    const float* b1       = (const float*)d_in[5];
    const float* W2       = (const float*)d_in[6];
    const float* att_src2 = (const float*)d_in[7];
    const float* att_dst2 = (const float*)d_in[8];
    const float* b2       = (const float*)d_in[9];
    const float* Wm1      = (const float*)d_in[10];
    const float* bm1      = (const float*)d_in[11];
    const float* Wm2      = (const float*)d_in[12];
    const float* bm2      = (const float*)d_in[13];
    float* out = (float*)d_out;

    int E = in_sizes[1] / 2;
    const int* srcp = eidx;
    const int* dstp = eidx + E;

    float *h1p, *h2p;
    __nv_bfloat16 *a1p, *a2p, *w1p, *w2p;
    cudaGetSymbolAddress((void**)&h1p, g_h1);
    cudaGetSymbolAddress((void**)&h2p, g_h2);
    cudaGetSymbolAddress((void**)&a1p, g_A1);
    cudaGetSymbolAddress((void**)&a2p, g_A2);
    cudaGetSymbolAddress((void**)&w1p, g_W1p);
    cudaGetSymbolAddress((void**)&w2p, g_W2p);

    // dynamic smem sizes: 2*(16KB A + BN*128B B)
    const int SMEM1 = 2 * (16384 + 128 * 128);  // 64KB
    const int SMEM2 = 2 * (16384 + 64 * 128);   // 48KB
    cudaFuncSetAttribute(k_gemm_bf16<128, 2, 4>,
                         cudaFuncAttributeMaxDynamicSharedMemorySize, SMEM1);
    cudaFuncSetAttribute(k_gemm_bf16<64, 2, 2>,
                         cudaFuncAttributeMaxDynamicSharedMemorySize, SMEM2);

    // split-bf16 packing (inputs + weights)
    k_packA1<<<(NN * KP1 + 255) / 256, 256>>>(x);
    k_packW<<<(KP1 * D1 + 255) / 256, 256>>>(W1, w1p, IN_CH, D1);
    k_packW<<<(KP2 * HID + 255) / 256, 256>>>(W2, w2p, D1, HID);

    // layer 1 GEMM (tensor cores, 3-term split-bf16)
    k_gemm_bf16<128, 2, 4><<<dim3(D1 / 128, (NN + 127) / 128), 256, SMEM1>>>(
        a1p, w1p, h1p, NN, D1, KP1);

    // CSR build (dst-grouped, with self loops)
    k_zero_deg<<<(NN + 255) / 256, 256>>>();
    k_count<<<(E + 255) / 256, 256>>>(dstp, E);
    k_scan1<<<NBLK, 1024>>>();
    k_scan2<<<1, 32>>>();
    k_scan3<<<(NN + 255) / 256, 256>>>();
    k_scatter<<<(E + NN + 255) / 256, 256>>>(srcp, dstp, E);

    // layer 1 attention + aggregation (packs A2 in epilogue)
    k_scores1<<<NN, 128>>>(att_src1, att_dst1);
    k_agg1<<<NN, 128>>>(b1);

    // layer 2
    k_gemm_bf16<64, 2, 2><<<dim3(HID / 64, (NN + 127) / 128), 128, SMEM2>>>(
        a2p, w2p, h2p, NN, HID, KP2);
    k_scores2<<<(NN + 7) / 8, 256>>>(att_src2, att_dst2);
    k_agg2<<<(NN + 3) / 4, 128>>>(b2);

    // MLP head
    k_mlp<<<(NN + 7) / 8, 256>>>(Wm1, bm1, Wm2, bm2, out);
}

// round 6
// speedup vs baseline: 1.1389x; 1.1389x over previous
#include <cuda_runtime.h>
#include <cuda_bf16.h>
#include <cstdint>

#define NN 50000
#define EMAX 800000
#define ETOT (EMAX + NN)
#define IN_CH 128
#define HID 64
#define HEADS 4
#define D1 (HEADS * HID)   // 256
#define NBLK 49            // ceil(NN/1024)
#define KP1 (3 * IN_CH)    // 384  3-term split-bf16 K for GEMM1
#define KP2 (3 * D1)       // 768  3-term split-bf16 K for GEMM2

// ---------------- scratch (static device globals; no runtime alloc) --------
__device__ __align__(128) float g_h1[NN * D1];
__device__ __align__(128) float g_h2[NN * HID];
__device__ __align__(128) float g_buf2[NN * HID];
__device__ __align__(128) __nv_bfloat16 g_A1[(size_t)NN * KP1];
__device__ __align__(128) __nv_bfloat16 g_A2[(size_t)NN * KP2];
__device__ __align__(128) __nv_bfloat16 g_W1p[(size_t)KP1 * D1];
__device__ __align__(128) __nv_bfloat16 g_W2p[(size_t)KP2 * HID];
__device__ __align__(128) float g_asrc1[NN * HEADS];
__device__ __align__(128) float g_adst1[NN * HEADS];
__device__ __align__(128) float g_asrc2[NN];
__device__ __align__(128) float g_adst2[NN];
__device__ __align__(128) float g_esc[(size_t)HEADS * ETOT];
__device__ __align__(128) int   g_deg[NN];
__device__ __align__(128) int   g_rowptr[NN + 1];
__device__ __align__(128) int   g_cursor[NN];
__device__ __align__(128) int   g_esrc[ETOT];
__device__ __align__(128) int   g_part[64];

// ---------------- CSR build -------------------------------------------------
__global__ void k_zero_deg() {
    int i = blockIdx.x * blockDim.x + threadIdx.x;
    if (i < NN) g_deg[i] = 0;
}

__global__ void k_count(const int* __restrict__ dst, int E) {
    int i = blockIdx.x * blockDim.x + threadIdx.x;
    if (i < E) atomicAdd(&g_deg[dst[i]], 1);
}

__global__ void k_scan1() {
    __shared__ int ws[32];
    int t = threadIdx.x;
    int i = blockIdx.x * 1024 + t;
    int v = (i < NN) ? (g_deg[i] + 1) : 0;
    int x = v;
    #pragma unroll
    for (int o = 1; o < 32; o <<= 1) {
        int y = __shfl_up_sync(0xFFFFFFFF, x, o);
        if ((t & 31) >= o) x += y;
    }
    if ((t & 31) == 31) ws[t >> 5] = x;
    __syncthreads();
    if (t < 32) {
        int s = ws[t];
        #pragma unroll
        for (int o = 1; o < 32; o <<= 1) {
            int y = __shfl_up_sync(0xFFFFFFFF, s, o);
            if (t >= o) s += y;
        }
        ws[t] = s;
    }
    __syncthreads();
    int incl = x + ((t >= 32) ? ws[(t >> 5) - 1] : 0);
    if (i < NN) g_rowptr[i + 1] = incl;
    if (t == 1023) g_part[blockIdx.x] = incl;
}

__global__ void k_scan2() {
    int l = threadIdx.x;
    int a = (l < NBLK) ? g_part[l] : 0;
    int b = (l + 32 < NBLK) ? g_part[l + 32] : 0;
    int ia = a;
    #pragma unroll
    for (int o = 1; o < 32; o <<= 1) {
        int y = __shfl_up_sync(0xFFFFFFFF, ia, o);
        if (l >= o) ia += y;
    }
    int tot = __shfl_sync(0xFFFFFFFF, ia, 31);
    int ib = b;
    #pragma unroll
    for (int o = 1; o < 32; o <<= 1) {
        int y = __shfl_up_sync(0xFFFFFFFF, ib, o);
        if (l >= o) ib += y;
    }
    g_part[l] = ia - a;
    g_part[l + 32] = tot + ib - b;
}

__global__ void k_scan3() {
    int i = blockIdx.x * blockDim.x + threadIdx.x;
    if (i >= NN) return;
    int off = g_part[i >> 10];
    int rp = g_rowptr[i + 1] + off;
    g_rowptr[i + 1] = rp;
    g_cursor[i] = rp - (g_deg[i] + 1);
    if (i == 0) g_rowptr[0] = 0;
}

__global__ void k_scatter(const int* __restrict__ src, const int* __restrict__ dst, int E) {
    int i = blockIdx.x * blockDim.x + threadIdx.x;
    if (i < E) {
        int p = atomicAdd(&g_cursor[dst[i]], 1);
        g_esrc[p] = src[i];
    } else if (i < E + NN) {
        int n = i - E;
        int p = atomicAdd(&g_cursor[n], 1);
        g_esrc[p] = n;
    }
}

// ---------------- 3-term split-bf16 packing ---------------------------------
// (hiA+loA)(hiB+loB) ~= hiA*hiB + hiA*loB + loA*hiB  (drop lo*lo ~2^-16 rel)
// A pattern per k: [hi, hi, lo]   B pattern per k: [hi, lo, hi]
__device__ __forceinline__ void split_bf16(float f, __nv_bfloat16& hi, __nv_bfloat16& lo) {
    hi = __float2bfloat16(f);
    lo = __float2bfloat16(f - __bfloat162float(hi));
}

__global__ void k_packA1(const float* __restrict__ x) {
    int i = blockIdx.x * blockDim.x + threadIdx.x;  // over NN*IN_CH/2
    if (i >= NN * (IN_CH / 2)) return;
    int m = i / (IN_CH / 2), kk = i - m * (IN_CH / 2);
    float2 v = reinterpret_cast<const float2*>(x)[i];
    __nv_bfloat16 h0, l0, h1, l1;
    split_bf16(v.x, h0, l0);
    split_bf16(v.y, h1, l1);
    __nv_bfloat162* p = reinterpret_cast<__nv_bfloat162*>(g_A1 + (size_t)m * KP1 + 6 * kk);
    p[0] = __halves2bfloat162(h0, h0);
    p[1] = __halves2bfloat162(l0, h1);
    p[2] = __halves2bfloat162(h1, l1);
}

__global__ void k_packW(const float* __restrict__ W, __nv_bfloat16* __restrict__ dst,
                        int K, int N) {
    int i = blockIdx.x * blockDim.x + threadIdx.x;
    if (i >= K * N) return;
    int k = i / N, n = i - k * N;
    __nv_bfloat16 hi, lo;
    split_bf16(W[i], hi, lo);
    size_t base = (size_t)(3 * k) * N + n;
    dst[base]         = hi;
    dst[base + N]     = lo;
    dst[base + 2 * N] = hi;
}

// ---------------- bf16 tensor-core GEMM ------------------------------------
// BM=128, BK=64, warp tile (MT*16) x 32, WM x WN warps, bf16 in / fp32 out
__device__ __forceinline__ void cp16(uint32_t dst, const void* src, int sz) {
    asm volatile("cp.async.ca.shared.global [%0], [%1], 16, %2;\n"
                 :: "r"(dst), "l"(src), "r"(sz));
}
__device__ __forceinline__ void ldsm4(uint32_t* r, uint32_t a) {
    asm volatile("ldmatrix.sync.aligned.m8n8.x4.shared.b16 {%0,%1,%2,%3}, [%4];"
                 : "=r"(r[0]), "=r"(r[1]), "=r"(r[2]), "=r"(r[3]) : "r"(a));
}
__device__ __forceinline__ void ldsm4t(uint32_t* r, uint32_t a) {
    asm volatile("ldmatrix.sync.aligned.m8n8.x4.trans.shared.b16 {%0,%1,%2,%3}, [%4];"
                 : "=r"(r[0]), "=r"(r[1]), "=r"(r[2]), "=r"(r[3]) : "r"(a));
}
__device__ __forceinline__ void mma16816(float* c, const uint32_t* a, uint32_t b0, uint32_t b1) {
    asm volatile("mma.sync.aligned.m16n8k16.row.col.f32.bf16.bf16.f32 "
                 "{%0,%1,%2,%3}, {%4,%5,%6,%7}, {%8,%9}, {%0,%1,%2,%3};"
                 : "+f"(c[0]), "+f"(c[1]), "+f"(c[2]), "+f"(c[3])
                 : "r"(a[0]), "r"(a[1]), "r"(a[2]), "r"(a[3]), "r"(b0), "r"(b1));
}
__device__ __forceinline__ uint32_t sw128(uint32_t off) {
    return off ^ ((off >> 3) & 0x70);
}

template<int BN, int WM, int WN, int MT>
__global__ __launch_bounds__(WM * WN * 32) void k_gemm_bf16(
        const __nv_bfloat16* __restrict__ A, const __nv_bfloat16* __restrict__ B,
        float* __restrict__ C, int M, int N, int Kp) {
    constexpr int THREADS = WM * WN * 32;
    constexpr int ASTG = 128 * 128;      // 16KB per stage (128 rows x 128B)
    constexpr int BSTG = 64 * BN * 2;    // 64 rows x BN bf16
    extern __shared__ __align__(1024) char smem_raw[];
    uint32_t sA = (uint32_t)__cvta_generic_to_shared(smem_raw);
    uint32_t sB = sA + 2 * ASTG;
    int t = threadIdx.x;
    int warp = t >> 5, lane = t & 31;
    int wm = warp & (WM - 1), wn = warp / WM;
    int row0 = blockIdx.y * 128, col0 = blockIdx.x * BN;

    float acc[MT][4][4];
    #pragma unroll
    for (int mt = 0; mt < MT; mt++)
        #pragma unroll
        for (int nt = 0; nt < 4; nt++)
            #pragma unroll
            for (int r = 0; r < 4; r++) acc[mt][nt][r] = 0.f;

    int nIter = Kp >> 6;

    auto load_tiles = [&](int it, int buf) {
        int k0 = it << 6;
        #pragma unroll
        for (int i = 0; i < 1024 / THREADS; i++) {   // A: 128 rows x 8 x 16B
            int id = t + i * THREADS;
            int r = id >> 3, kc = id & 7;
            uint32_t off = sw128(r * 128 + kc * 16);
            int sz = (row0 + r < M) ? 16 : 0;
            cp16(sA + buf * ASTG + off, A + (size_t)(row0 + r) * Kp + k0 + kc * 8, sz);
        }
        #pragma unroll
        for (int i = 0; i < (64 * BN / 8) / THREADS; i++) {  // B: 64 rows x BN/8 x 16B
            int id = t + i * THREADS;
            int r = id / (BN / 8), c = id % (BN / 8);
            int n0 = c * 8;
            uint32_t off = (uint32_t)(n0 >> 6) * 8192 + sw128(r * 128 + (n0 & 63) * 2);
            cp16(sB + buf * BSTG + off, B + (size_t)(k0 + r) * N + col0 + n0, 16);
        }
        asm volatile("cp.async.commit_group;\n" ::: "memory");
    };

    load_tiles(0, 0);
    for (int it = 0; it < nIter; it++) {
        int buf = it & 1;
        if (it + 1 < nIter) {
            load_tiles(it + 1, buf ^ 1);
            asm volatile("cp.async.wait_group 1;\n" ::: "memory");
        } else {
            asm volatile("cp.async.wait_group 0;\n" ::: "memory");
        }
        __syncthreads();
        uint32_t aBuf = sA + buf * ASTG;
        uint32_t bBuf = sB + buf * BSTG;
        #pragma unroll
        for (int kk = 0; kk < 4; kk++) {
            int k0 = kk << 4;
            uint32_t afr[MT][4], bfr[2][4];
            #pragma unroll
            for (int mt = 0; mt < MT; mt++) {
                int r = wm * (MT * 16) + mt * 16 + (lane & 15);
                uint32_t off = sw128(r * 128 + (k0 + (lane >> 4) * 8) * 2);
                ldsm4(afr[mt], aBuf + off);
            }
            #pragma unroll
            for (int np = 0; np < 2; np++) {
                int k = k0 + (lane & 7) + ((lane >> 3) & 1) * 8;
                int n = wn * 32 + np * 16 + (lane >> 4) * 8;
                uint32_t off = (uint32_t)(n >> 6) * 8192 + sw128(k * 128 + (n & 63) * 2);
                ldsm4t(bfr[np], bBuf + off);
            }
            #pragma unroll
            for (int mt = 0; mt < MT; mt++)
                #pragma unroll
                for (int nt = 0; nt < 4; nt++)
                    mma16816(acc[mt][nt], afr[mt],
                             bfr[nt >> 1][(nt & 1) * 2], bfr[nt >> 1][(nt & 1) * 2 + 1]);
        }
        __syncthreads();
    }

    #pragma unroll
    for (int mt = 0; mt < MT; mt++)
        #pragma unroll
        for (int nt = 0; nt < 4; nt++) {
            int r = row0 + wm * (MT * 16) + mt * 16 + (lane >> 2);
            int cn = col0 + wn * 32 + nt * 8 + (lane & 3) * 2;
            if (r < M) {
                C[(size_t)r * N + cn]     = acc[mt][nt][0];
                C[(size_t)r * N + cn + 1] = acc[mt][nt][1];
            }
            if (r + 8 < M) {
                C[(size_t)(r + 8) * N + cn]     = acc[mt][nt][2];
                C[(size_t)(r + 8) * N + cn + 1] = acc[mt][nt][3];
            }
        }
}

// ---------------- attention scores -----------------------------------------
__global__ void k_scores1(const float* __restrict__ att_src, const float* __restrict__ att_dst) {
    int n = blockIdx.x;
    int t = threadIdx.x;
    int h = t >> 5, lane = t & 31;
    const float* hp = g_h1 + (size_t)n * D1 + h * HID;
    float s1 = hp[lane] * att_src[h * HID + lane] + hp[lane + 32] * att_src[h * HID + lane + 32];
    float s2 = hp[lane] * att_dst[h * HID + lane] + hp[lane + 32] * att_dst[h * HID + lane + 32];
    #pragma unroll
    for (int o = 16; o; o >>= 1) {
        s1 += __shfl_down_sync(0xFFFFFFFF, s1, o);
        s2 += __shfl_down_sync(0xFFFFFFFF, s2, o);
    }
    if (lane == 0) {
        g_asrc1[n * HEADS + h] = s1;
        g_adst1[n * HEADS + h] = s2;
    }
}

__global__ void k_scores2(const float* __restrict__ att_src, const float* __restrict__ att_dst) {
    int w = threadIdx.x >> 5, lane = threadIdx.x & 31;
    int n = blockIdx.x * 8 + w;
    if (n >= NN) return;
    const float* hp = g_h2 + (size_t)n * HID;
    float s1 = hp[lane] * att_src[lane] + hp[lane + 32] * att_src[lane + 32];
    float s2 = hp[lane] * att_dst[lane] + hp[lane + 32] * att_dst[lane + 32];
    #pragma unroll
    for (int o = 16; o; o >>= 1) {
        s1 += __shfl_down_sync(0xFFFFFFFF, s1, o);
        s2 += __shfl_down_sync(0xFFFFFFFF, s2, o);
    }
    if (lane == 0) {
        g_asrc2[n] = s1;
        g_adst2[n] = s2;
    }
}

// ---------------- aggregation ----------------------------------------------
__device__ __forceinline__ float lrelu(float x) { return x > 0.f ? x : 0.2f * x; }

// layer 1: one node per 128-thread block; warp h = head h; epilogue packs A2
__global__ void k_agg1(const float* __restrict__ bias) {
    int n = blockIdx.x;
    int t = threadIdx.x;
    int h = t >> 5, lane = t & 31;
    int beg = g_rowptr[n], end = g_rowptr[n + 1];
    float ad = g_adst1[n * HEADS + h];
    float* esc = g_esc + (size_t)h * ETOT;

    float m = -1e30f, d = 0.f;
    for (int e = beg + lane; e < end; e += 32) {
        int s = g_esrc[e];
        float x = lrelu(g_asrc1[s * HEADS + h] + ad);
        esc[e] = x;
        float mn = fmaxf(m, x);
        d = d * __expf(m - mn) + __expf(x - mn);
        m = mn;
    }
    #pragma unroll
    for (int o = 16; o; o >>= 1) {
        float mo = __shfl_xor_sync(0xFFFFFFFF, m, o);
        float dd = __shfl_xor_sync(0xFFFFFFFF, d, o);
        float mn = fmaxf(m, mo);
        d = d * __expf(m - mn) + dd * __expf(mo - mn);
        m = mn;
    }
    float inv = 1.f / (d + 1e-16f);
    __syncwarp();

    float2 acc = make_float2(0.f, 0.f);
    int c = lane << 1;
    const float* hrow = g_h1 + h * HID + c;
    for (int e0 = beg; e0 < end; e0 += 32) {
        int e = e0 + lane;
        int s = 0; float w = 0.f;
        if (e < end) {
            s = g_esrc[e];
            w = __expf(esc[e] - m) * inv;
        }
        int cnt = min(32, end - e0);
        for (int j = 0; j < cnt; j++) {
            int   sj = __shfl_sync(0xFFFFFFFF, s, j);
            float wj = __shfl_sync(0xFFFFFFFF, w, j);
            float2 v = *reinterpret_cast<const float2*>(hrow + (size_t)sj * D1);
            acc.x += v.x * wj;
            acc.y += v.y * wj;
        }
    }
    int j0 = h * HID + c;
    float v0 = acc.x + bias[j0];
    float v1 = acc.y + bias[j0 + 1];
    v0 = v0 > 0.f ? v0 : __expf(v0) - 1.f;   // elu
    v1 = v1 > 0.f ? v1 : __expf(v1) - 1.f;
    __nv_bfloat16 h0, l0, h1, l1;
    split_bf16(v0, h0, l0);
    split_bf16(v1, h1, l1);
    // pattern per element: [hi, hi, lo]; 2 elements -> 6 bf16 at 3*j0
    __nv_bfloat162* p = reinterpret_cast<__nv_bfloat162*>(g_A2 + (size_t)n * KP2 + 3 * j0);
    p[0] = __halves2bfloat162(h0, h0);
    p[1] = __halves2bfloat162(l0, h1);
    p[2] = __halves2bfloat162(h1, l1);
}

// layer 2: one node per warp
__global__ void k_agg2(const float* __restrict__ bias) {
    int w = threadIdx.x >> 5, lane = threadIdx.x & 31;
    int n = blockIdx.x * 4 + w;
    if (n >= NN) return;
    int beg = g_rowptr[n], end = g_rowptr[n + 1];
    float ad = g_adst2[n];

    float m = -1e30f, d = 0.f;
    for (int e = beg + lane; e < end; e += 32) {
        int s = g_esrc[e];
        float x = lrelu(g_asrc2[s] + ad);
        g_esc[e] = x;
        float mn = fmaxf(m, x);
        d = d * __expf(m - mn) + __expf(x - mn);
        m = mn;
    }
    #pragma unroll
    for (int o = 16; o; o >>= 1) {
        float mo = __shfl_xor_sync(0xFFFFFFFF, m, o);
        float dd = __shfl_xor_sync(0xFFFFFFFF, d, o);
        float mn = fmaxf(m, mo);
        d = d * __expf(m - mn) + dd * __expf(mo - mn);
        m = mn;
    }
    float inv = 1.f / (d + 1e-16f);
    __syncwarp();

    float2 acc = make_float2(0.f, 0.f);
    int c = lane << 1;
    for (int e0 = beg; e0 < end; e0 += 32) {
        int e = e0 + lane;
        int s = 0; float wt = 0.f;
        if (e < end) {
            s = g_esrc[e];
            wt = __expf(g_esc[e] - m) * inv;
        }
        int cnt = min(32, end - e0);
        for (int j = 0; j < cnt; j++) {
            int   sj = __shfl_sync(0xFFFFFFFF, s, j);
            float wj = __shfl_sync(0xFFFFFFFF, wt, j);
            float2 v = *reinterpret_cast<const float2*>(g_h2 + (size_t)sj * HID + c);
            acc.x += v.x * wj;
            acc.y += v.y * wj;
        }
    }
    float v0 = acc.x + bias[c];
    float v1 = acc.y + bias[c + 1];
    g_buf2[(size_t)n * HID + c]     = v0 > 0.f ? v0 : __expf(v0) - 1.f;
    g_buf2[(size_t)n * HID + c + 1] = v1 > 0.f ? v1 : __expf(v1) - 1.f;
}

// ---------------- fused MLP head -------------------------------------------
__global__ void k_mlp(const float* __restrict__ Wm1, const float* __restrict__ bm1,
                      const float* __restrict__ Wm2, const float* __restrict__ bm2,
                      float* __restrict__ out) {
    __shared__ float sW1[HID * 32];
    __shared__ float sW2[32 * 2];
    __shared__ float sb1[32], sb2[2];
    __shared__ float hm[8][33];
    int t = threadIdx.x;
    for (int i = t; i < HID * 32; i += 256) sW1[i] = Wm1[i];
    if (t < 64) sW2[t] = Wm2[t];
    if (t < 32) sb1[t] = bm1[t];
    if (t < 2)  sb2[t] = bm2[t];
    __syncthreads();
    int nl = t >> 5, j = t & 31;
    int node = blockIdx.x * 8 + nl;
    if (node < NN) {
        const float* hrow = g_buf2 + (size_t)node * HID;
        float acc = sb1[j];
        #pragma unroll
        for (int k = 0; k < HID; k++) acc += hrow[k] * sW1[k * 32 + j];
        hm[nl][j] = fmaxf(acc, 0.f);
    }
    __syncthreads();
    if (node < NN && j < 2) {
        float acc = sb2[j];
        #pragma unroll
        for (int k = 0; k < 32; k++) acc += hm[nl][k] * sW2[k * 2 + j];
        out[node * 2 + j] = acc;
    }
}

// ---------------- launch ----------------------------------------------------
extern "C" void kernel_launch(void* const* d_in, const int* in_sizes, int n_in,
                              void* d_out, int out_size) {
    const float* x        = (const float*)d_in[0];
    const int*   eidx     = (const int*)d_in[1];
    const float* W1       = (const float*)d_in[2];
    const float* att_src1 = (const float*)d_in[3];
    const float* att_dst1 = (const float*)d_in[4];
    const float* b1       = (const float*)d_in[5];
    const float* W2       = (const float*)d_in[6];
    const float* att_src2 = (const float*)d_in[7];
    const float* att_dst2 = (const float*)d_in[8];
    const float* b2       = (const float*)d_in[9];
    const float* Wm1      = (const float*)d_in[10];
    const float* bm1      = (const float*)d_in[11];
    const float* Wm2      = (const float*)d_in[12];
    const float* bm2      = (const float*)d_in[13];
    float* out = (float*)d_out;

    int E = in_sizes[1] / 2;
    const int* srcp = eidx;
    const int* dstp = eidx + E;

    float *h1p, *h2p;
    __nv_bfloat16 *a1p, *a2p, *w1p, *w2p;
    cudaGetSymbolAddress((void**)&h1p, g_h1);
    cudaGetSymbolAddress((void**)&h2p, g_h2);
    cudaGetSymbolAddress((void**)&a1p, g_A1);
    cudaGetSymbolAddress((void**)&a2p, g_A2);
    cudaGetSymbolAddress((void**)&w1p, g_W1p);
    cudaGetSymbolAddress((void**)&w2p, g_W2p);

    // dynamic smem: 2*(16KB A + BN*128B B)
    const int SMEM1 = 2 * (16384 + 128 * 128);  // 64KB
    const int SMEM2 = 2 * (16384 + 64 * 128);   // 48KB
    cudaFuncSetAttribute(k_gemm_bf16<128, 2, 4, 4>,
                         cudaFuncAttributeMaxDynamicSharedMemorySize, SMEM1);
    cudaFuncSetAttribute(k_gemm_bf16<64, 4, 2, 2>,
                         cudaFuncAttributeMaxDynamicSharedMemorySize, SMEM2);

    // side stream + events, created once (no destroys mid-capture)
    static cudaStream_t s2 = nullptr;
    static cudaEvent_t evFork = nullptr, evJoin = nullptr;
    if (!s2) {
        cudaStreamCreateWithFlags(&s2, cudaStreamNonBlocking);
        cudaEventCreateWithFlags(&evFork, cudaEventDisableTiming);
        cudaEventCreateWithFlags(&evJoin, cudaEventDisableTiming);
    }

    // fork: CSR build + W2 pack on s2, concurrent with pack/GEMM1/scores1
    cudaEventRecord(evFork, 0);
    cudaStreamWaitEvent(s2, evFork, 0);

    k_zero_deg<<<(NN + 255) / 256, 256, 0, s2>>>();
    k_count<<<(E + 255) / 256, 256, 0, s2>>>(dstp, E);
    k_scan1<<<NBLK, 1024, 0, s2>>>();
    k_scan2<<<1, 32, 0, s2>>>();
    k_scan3<<<(NN + 255) / 256, 256, 0, s2>>>();
    k_scatter<<<(E + NN + 255) / 256, 256, 0, s2>>>(srcp, dstp, E);
    k_packW<<<(D1 * HID + 255) / 256, 256, 0, s2>>>(W2, w2p, D1, HID);
    cudaEventRecord(evJoin, s2);

    // main path
    k_packA1<<<(NN * (IN_CH / 2) + 255) / 256, 256>>>(x);
    k_packW<<<(IN_CH * D1 + 255) / 256, 256>>>(W1, w1p, IN_CH, D1);
    k_gemm_bf16<128, 2, 4, 4><<<dim3(D1 / 128, (NN + 127) / 128), 256, SMEM1>>>(
        a1p, w1p, h1p, NN, D1, KP1);
    k_scores1<<<NN, 128>>>(att_src1, att_dst1);

    // join: agg1 needs CSR; GEMM2 needs W2 pack
    cudaStreamWaitEvent(0, evJoin, 0);
    k_agg1<<<NN, 128>>>(b1);

    // layer 2
    k_gemm_bf16<64, 4, 2, 2><<<dim3(HID / 64, (NN + 127) / 128), 256, SMEM2>>>(
        a2p, w2p, h2p, NN, HID, KP2);
    k_scores2<<<(NN + 7) / 8, 256>>>(att_src2, att_dst2);
    k_agg2<<<(NN + 3) / 4, 128>>>(b2);

    // MLP head
    k_mlp<<<(NN + 7) / 8, 256>>>(Wm1, bm1, Wm2, bm2, out);
}

// round 7
// speedup vs baseline: 1.3424x; 1.1787x over previous
#include <cuda_runtime.h>
#include <cuda_bf16.h>
#include <cstdint>

#define NN 50000
#define EMAX 800000
#define ETOT (EMAX + NN)
#define IN_CH 128
#define HID 64
#define HEADS 4
#define D1 (HEADS * HID)   // 256
#define NBLK 49            // ceil(NN/1024)
#define KP1 (3 * IN_CH)    // 384  3-term split-bf16 K for GEMM1
#define KP2 (3 * D1)       // 768  3-term split-bf16 K for GEMM2

// ---------------- scratch (static device globals; no runtime alloc) --------
__device__ __align__(128) float g_h1[NN * D1];
__device__ __align__(128) float g_h2[NN * HID];
__device__ __align__(128) __nv_bfloat16 g_A1[(size_t)NN * KP1];
__device__ __align__(128) __nv_bfloat16 g_A2[(size_t)NN * KP2];
__device__ __align__(128) __nv_bfloat16 g_W1p[(size_t)KP1 * D1];
__device__ __align__(128) __nv_bfloat16 g_W2p[(size_t)KP2 * HID];
__device__ __align__(128) float g_asrc1[NN * HEADS];
__device__ __align__(128) float g_adst1[NN * HEADS];
__device__ __align__(128) float g_asrc2[NN];
__device__ __align__(128) float g_adst2[NN];
__device__ __align__(128) float g_esc[(size_t)HEADS * ETOT];
__device__ __align__(128) int   g_deg[NN];
__device__ __align__(128) int   g_rowptr[NN + 1];
__device__ __align__(128) int   g_cursor[NN];
__device__ __align__(128) int   g_esrc[ETOT];
__device__ __align__(128) int   g_part[64];

// ---------------- CSR build -------------------------------------------------
__global__ void k_zero_deg() {
    int i = blockIdx.x * blockDim.x + threadIdx.x;
    if (i < NN) g_deg[i] = 0;
}

__global__ void k_count(const int* __restrict__ dst, int E) {
    int i = blockIdx.x * blockDim.x + threadIdx.x;
    if (i < E) atomicAdd(&g_deg[dst[i]], 1);
}

__global__ void k_scan1() {
    __shared__ int ws[32];
    int t = threadIdx.x;
    int i = blockIdx.x * 1024 + t;
    int v = (i < NN) ? (g_deg[i] + 1) : 0;
    int x = v;
    #pragma unroll
    for (int o = 1; o < 32; o <<= 1) {
        int y = __shfl_up_sync(0xFFFFFFFF, x, o);
        if ((t & 31) >= o) x += y;
    }
    if ((t & 31) == 31) ws[t >> 5] = x;
    __syncthreads();
    if (t < 32) {
        int s = ws[t];
        #pragma unroll
        for (int o = 1; o < 32; o <<= 1) {
            int y = __shfl_up_sync(0xFFFFFFFF, s, o);
            if (t >= o) s += y;
        }
        ws[t] = s;
    }
    __syncthreads();
    int incl = x + ((t >= 32) ? ws[(t >> 5) - 1] : 0);
    if (i < NN) g_rowptr[i + 1] = incl;
    if (t == 1023) g_part[blockIdx.x] = incl;
}

__global__ void k_scan2() {
    int l = threadIdx.x;
    int a = (l < NBLK) ? g_part[l] : 0;
    int b = (l + 32 < NBLK) ? g_part[l + 32] : 0;
    int ia = a;
    #pragma unroll
    for (int o = 1; o < 32; o <<= 1) {
        int y = __shfl_up_sync(0xFFFFFFFF, ia, o);
        if (l >= o) ia += y;
    }
    int tot = __shfl_sync(0xFFFFFFFF, ia, 31);
    int ib = b;
    #pragma unroll
    for (int o = 1; o < 32; o <<= 1) {
        int y = __shfl_up_sync(0xFFFFFFFF, ib, o);
        if (l >= o) ib += y;
    }
    g_part[l] = ia - a;
    g_part[l + 32] = tot + ib - b;
}

__global__ void k_scan3() {
    int i = blockIdx.x * blockDim.x + threadIdx.x;
    if (i >= NN) return;
    int off = g_part[i >> 10];
    int rp = g_rowptr[i + 1] + off;
    g_rowptr[i + 1] = rp;
    g_cursor[i] = rp - (g_deg[i] + 1);
    if (i == 0) g_rowptr[0] = 0;
}

__global__ void k_scatter(const int* __restrict__ src, const int* __restrict__ dst, int E) {
    int i = blockIdx.x * blockDim.x + threadIdx.x;
    if (i < E) {
        int p = atomicAdd(&g_cursor[dst[i]], 1);
        g_esrc[p] = src[i];
    } else if (i < E + NN) {
        int n = i - E;
        int p = atomicAdd(&g_cursor[n], 1);
        g_esrc[p] = n;
    }
}

// ---------------- 3-term split-bf16 packing ---------------------------------
// (hiA+loA)(hiB+loB) ~= hiA*hiB + hiA*loB + loA*hiB  (drop lo*lo ~2^-16 rel)
// A pattern per k: [hi, hi, lo]   B pattern per k: [hi, lo, hi]
__device__ __forceinline__ void split_bf16(float f, __nv_bfloat16& hi, __nv_bfloat16& lo) {
    hi = __float2bfloat16(f);
    lo = __float2bfloat16(f - __bfloat162float(hi));
}

__global__ void k_packA1(const float* __restrict__ x) {
    int i = blockIdx.x * blockDim.x + threadIdx.x;  // over NN*IN_CH/2
    if (i >= NN * (IN_CH / 2)) return;
    int m = i / (IN_CH / 2), kk = i - m * (IN_CH / 2);
    float2 v = reinterpret_cast<const float2*>(x)[i];
    __nv_bfloat16 h0, l0, h1, l1;
    split_bf16(v.x, h0, l0);
    split_bf16(v.y, h1, l1);
    __nv_bfloat162* p = reinterpret_cast<__nv_bfloat162*>(g_A1 + (size_t)m * KP1 + 6 * kk);
    p[0] = __halves2bfloat162(h0, h0);
    p[1] = __halves2bfloat162(l0, h1);
    p[2] = __halves2bfloat162(h1, l1);
}

__global__ void k_packW(const float* __restrict__ W, __nv_bfloat16* __restrict__ dst,
                        int K, int N) {
    int i = blockIdx.x * blockDim.x + threadIdx.x;
    if (i >= K * N) return;
    int k = i / N, n = i - k * N;
    __nv_bfloat16 hi, lo;
    split_bf16(W[i], hi, lo);
    size_t base = (size_t)(3 * k) * N + n;
    dst[base]         = hi;
    dst[base + N]     = lo;
    dst[base + 2 * N] = hi;
}

// ---------------- bf16 tensor-core GEMM + fused attention scores -----------
// BM=128, BK=64, 3-stage cp.async, warp tile (MT*16) x 32, WM x WN warps.
// NSC = heads covered by CTA (BN/64). Epilogue computes a_src/a_dst per row.
__device__ __forceinline__ void cp16(uint32_t dst, const void* src, int sz) {
    asm volatile("cp.async.ca.shared.global [%0], [%1], 16, %2;\n"
                 :: "r"(dst), "l"(src), "r"(sz));
}
__device__ __forceinline__ void ldsm4(uint32_t* r, uint32_t a) {
    asm volatile("ldmatrix.sync.aligned.m8n8.x4.shared.b16 {%0,%1,%2,%3}, [%4];"
                 : "=r"(r[0]), "=r"(r[1]), "=r"(r[2]), "=r"(r[3]) : "r"(a));
}
__device__ __forceinline__ void ldsm4t(uint32_t* r, uint32_t a) {
    asm volatile("ldmatrix.sync.aligned.m8n8.x4.trans.shared.b16 {%0,%1,%2,%3}, [%4];"
                 : "=r"(r[0]), "=r"(r[1]), "=r"(r[2]), "=r"(r[3]) : "r"(a));
}
__device__ __forceinline__ void mma16816(float* c, const uint32_t* a, uint32_t b0, uint32_t b1) {
    asm volatile("mma.sync.aligned.m16n8k16.row.col.f32.bf16.bf16.f32 "
                 "{%0,%1,%2,%3}, {%4,%5,%6,%7}, {%8,%9}, {%0,%1,%2,%3};"
                 : "+f"(c[0]), "+f"(c[1]), "+f"(c[2]), "+f"(c[3])
                 : "r"(a[0]), "r"(a[1]), "r"(a[2]), "r"(a[3]), "r"(b0), "r"(b1));
}
__device__ __forceinline__ uint32_t sw128(uint32_t off) {
    return off ^ ((off >> 3) & 0x70);
}

template<int BN, int WM, int WN, int MT, int NSC>
__global__ __launch_bounds__(WM * WN * 32) void k_gemm_bf16(
        const __nv_bfloat16* __restrict__ A, const __nv_bfloat16* __restrict__ B,
        float* __restrict__ C, int M, int N, int Kp,
        const float* __restrict__ att_src, const float* __restrict__ att_dst,
        float* __restrict__ asrc, float* __restrict__ adst, int heads_tot) {
    constexpr int THREADS = WM * WN * 32;
    constexpr int ASTG = 128 * 128;      // 16KB per stage
    constexpr int BSTG = 64 * BN * 2;
    extern __shared__ __align__(1024) char smem_raw[];
    uint32_t sA = (uint32_t)__cvta_generic_to_shared(smem_raw);
    uint32_t sB = sA + 3 * ASTG;
    int t = threadIdx.x;
    int warp = t >> 5, lane = t & 31;
    int wm = warp & (WM - 1), wn = warp / WM;
    int row0 = blockIdx.y * 128, col0 = blockIdx.x * BN;

    float acc[MT][4][4];
    #pragma unroll
    for (int mt = 0; mt < MT; mt++)
        #pragma unroll
        for (int nt = 0; nt < 4; nt++)
            #pragma unroll
            for (int r = 0; r < 4; r++) acc[mt][nt][r] = 0.f;

    int nIter = Kp >> 6;

    auto load_tiles = [&](int it, int buf) {
        int k0 = it << 6;
        #pragma unroll
        for (int i = 0; i < 1024 / THREADS; i++) {   // A: 128 rows x 8 x 16B
            int id = t + i * THREADS;
            int r = id >> 3, kc = id & 7;
            uint32_t off = sw128(r * 128 + kc * 16);
            int sz = (row0 + r < M) ? 16 : 0;
            cp16(sA + buf * ASTG + off, A + (size_t)(row0 + r) * Kp + k0 + kc * 8, sz);
        }
        #pragma unroll
        for (int i = 0; i < (64 * BN / 8) / THREADS; i++) {  // B
            int id = t + i * THREADS;
            int r = id / (BN / 8), c = id % (BN / 8);
            int n0 = c * 8;
            uint32_t off = (uint32_t)(n0 >> 6) * 8192 + sw128(r * 128 + (n0 & 63) * 2);
            cp16(sB + buf * BSTG + off, B + (size_t)(k0 + r) * N + col0 + n0, 16);
        }
        asm volatile("cp.async.commit_group;\n" ::: "memory");
    };

    load_tiles(0, 0);
    load_tiles(1, 1);
    for (int it = 0; it < nIter; it++) {
        int buf = it % 3;
        if (it + 2 < nIter) {
            load_tiles(it + 2, (it + 2) % 3);
            asm volatile("cp.async.wait_group 2;\n" ::: "memory");
        } else if (it + 1 < nIter) {
            asm volatile("cp.async.wait_group 1;\n" ::: "memory");
        } else {
            asm volatile("cp.async.wait_group 0;\n" ::: "memory");
        }
        __syncthreads();
        uint32_t aBuf = sA + buf * ASTG;
        uint32_t bBuf = sB + buf * BSTG;
        #pragma unroll
        for (int kk = 0; kk < 4; kk++) {
            int k0 = kk << 4;
            uint32_t afr[MT][4], bfr[2][4];
            #pragma unroll
            for (int mt = 0; mt < MT; mt++) {
                int r = wm * (MT * 16) + mt * 16 + (lane & 15);
                uint32_t off = sw128(r * 128 + (k0 + (lane >> 4) * 8) * 2);
                ldsm4(afr[mt], aBuf + off);
            }
            #pragma unroll
            for (int np = 0; np < 2; np++) {
                int k = k0 + (lane & 7) + ((lane >> 3) & 1) * 8;
                int n = wn * 32 + np * 16 + (lane >> 4) * 8;
                uint32_t off = (uint32_t)(n >> 6) * 8192 + sw128(k * 128 + (n & 63) * 2);
                ldsm4t(bfr[np], bBuf + off);
            }
            #pragma unroll
            for (int mt = 0; mt < MT; mt++)
                #pragma unroll
                for (int nt = 0; nt < 4; nt++)
                    mma16816(acc[mt][nt], afr[mt],
                             bfr[nt >> 1][(nt & 1) * 2], bfr[nt >> 1][(nt & 1) * 2 + 1]);
        }
        __syncthreads();
    }

    // ---- epilogue: write C + fused attention scores ----
    // pipeline smem is dead now; reuse its head for the score accumulator
    float* ssc = reinterpret_cast<float*>(smem_raw);   // [128][NSC][2]
    for (int i = t; i < 128 * NSC * 2; i += THREADS) ssc[i] = 0.f;
    __syncthreads();

    float psrc[MT][2], pdst[MT][2];
    #pragma unroll
    for (int mt = 0; mt < MT; mt++) {
        psrc[mt][0] = psrc[mt][1] = 0.f;
        pdst[mt][0] = pdst[mt][1] = 0.f;
    }

    #pragma unroll
    for (int mt = 0; mt < MT; mt++)
        #pragma unroll
        for (int nt = 0; nt < 4; nt++) {
            int r = row0 + wm * (MT * 16) + mt * 16 + (lane >> 2);
            int cn = col0 + wn * 32 + nt * 8 + (lane & 3) * 2;
            float a0s = att_src[cn], a1s = att_src[cn + 1];
            float a0d = att_dst[cn], a1d = att_dst[cn + 1];
            psrc[mt][0] += acc[mt][nt][0] * a0s + acc[mt][nt][1] * a1s;
            pdst[mt][0] += acc[mt][nt][0] * a0d + acc[mt][nt][1] * a1d;
            psrc[mt][1] += acc[mt][nt][2] * a0s + acc[mt][nt][3] * a1s;
            pdst[mt][1] += acc[mt][nt][2] * a0d + acc[mt][nt][3] * a1d;
            if (r < M) {
                C[(size_t)r * N + cn]     = acc[mt][nt][0];
                C[(size_t)r * N + cn + 1] = acc[mt][nt][1];
            }
            if (r + 8 < M) {
                C[(size_t)(r + 8) * N + cn]     = acc[mt][nt][2];
                C[(size_t)(r + 8) * N + cn + 1] = acc[mt][nt][3];
            }
        }

    // reduce over the 4 lanes of each row-quad, then smem-atomic combine
    int hh = (wn * 32) >> 6;          // head (within CTA) this warp's cols belong to
    #pragma unroll
    for (int mt = 0; mt < MT; mt++)
        #pragma unroll
        for (int rh = 0; rh < 2; rh++) {
            float s = psrc[mt][rh], d = pdst[mt][rh];
            s += __shfl_xor_sync(0xFFFFFFFF, s, 1);
            s += __shfl_xor_sync(0xFFFFFFFF, s, 2);
            d += __shfl_xor_sync(0xFFFFFFFF, d, 1);
            d += __shfl_xor_sync(0xFFFFFFFF, d, 2);
            if ((lane & 3) == 0) {
                int lr = wm * (MT * 16) + mt * 16 + (lane >> 2) + rh * 8;
                atomicAdd(&ssc[(lr * NSC + hh) * 2],     s);
                atomicAdd(&ssc[(lr * NSC + hh) * 2 + 1], d);
            }
        }
    __syncthreads();

    if (t < 128) {
        int row = row0 + t;
        if (row < M) {
            int h_base = col0 >> 6;
            #pragma unroll
            for (int h = 0; h < NSC; h++) {
                asrc[row * heads_tot + h_base + h] = ssc[(t * NSC + h) * 2];
                adst[row * heads_tot + h_base + h] = ssc[(t * NSC + h) * 2 + 1];
            }
        }
    }
}

// ---------------- aggregation ----------------------------------------------
__device__ __forceinline__ float lrelu(float x) { return x > 0.f ? x : 0.2f * x; }

// layer 1: one node per 128-thread block; warp h = head h; epilogue packs A2
__global__ void k_agg1(const float* __restrict__ bias) {
    int n = blockIdx.x;
    int t = threadIdx.x;
    int h = t >> 5, lane = t & 31;
    int beg = g_rowptr[n], end = g_rowptr[n + 1];
    float ad = g_adst1[n * HEADS + h];
    float* esc = g_esc + (size_t)h * ETOT;

    float m = -1e30f, d = 0.f;
    for (int e = beg + lane; e < end; e += 32) {
        int s = g_esrc[e];
        float x = lrelu(g_asrc1[s * HEADS + h] + ad);
        esc[e] = x;
        float mn = fmaxf(m, x);
        d = d * __expf(m - mn) + __expf(x - mn);
        m = mn;
    }
    #pragma unroll
    for (int o = 16; o; o >>= 1) {
        float mo = __shfl_xor_sync(0xFFFFFFFF, m, o);
        float dd = __shfl_xor_sync(0xFFFFFFFF, d, o);
        float mn = fmaxf(m, mo);
        d = d * __expf(m - mn) + dd * __expf(mo - mn);
        m = mn;
    }
    float inv = 1.f / (d + 1e-16f);
    __syncwarp();

    float2 acc = make_float2(0.f, 0.f);
    int c = lane << 1;
    const float* hrow = g_h1 + h * HID + c;
    for (int e0 = beg; e0 < end; e0 += 32) {
        int e = e0 + lane;
        int s = 0; float w = 0.f;
        if (e < end) {
            s = g_esrc[e];
            w = __expf(esc[e] - m) * inv;
        }
        int cnt = min(32, end - e0);
        for (int j = 0; j < cnt; j++) {
            int   sj = __shfl_sync(0xFFFFFFFF, s, j);
            float wj = __shfl_sync(0xFFFFFFFF, w, j);
            float2 v = *reinterpret_cast<const float2*>(hrow + (size_t)sj * D1);
            acc.x += v.x * wj;
            acc.y += v.y * wj;
        }
    }
    int j0 = h * HID + c;
    float v0 = acc.x + bias[j0];
    float v1 = acc.y + bias[j0 + 1];
    v0 = v0 > 0.f ? v0 : __expf(v0) - 1.f;   // elu
    v1 = v1 > 0.f ? v1 : __expf(v1) - 1.f;
    __nv_bfloat16 h0, l0, h1, l1;
    split_bf16(v0, h0, l0);
    split_bf16(v1, h1, l1);
    __nv_bfloat162* p = reinterpret_cast<__nv_bfloat162*>(g_A2 + (size_t)n * KP2 + 3 * j0);
    p[0] = __halves2bfloat162(h0, h0);
    p[1] = __halves2bfloat162(l0, h1);
    p[2] = __halves2bfloat162(h1, l1);
}

// layer 2 aggregation + fused MLP head: 8 nodes per 256-thread block
__global__ __launch_bounds__(256) void k_agg2_mlp(
        const float* __restrict__ bias,
        const float* __restrict__ Wm1, const float* __restrict__ bm1,
        const float* __restrict__ Wm2, const float* __restrict__ bm2,
        float* __restrict__ out) {
    __shared__ float sW1[HID * 32];
    __shared__ float sW2[64];
    __shared__ float sb1[32], sb2v[2];
    int t = threadIdx.x;
    for (int i = t; i < HID * 32; i += 256) sW1[i] = Wm1[i];
    if (t < 64) sW2[t] = Wm2[t];
    if (t < 32) sb1[t] = bm1[t];
    if (t < 2)  sb2v[t] = bm2[t];
    __syncthreads();

    int w = t >> 5, lane = t & 31;
    int n = blockIdx.x * 8 + w;
    if (n >= NN) return;
    int beg = g_rowptr[n], end = g_rowptr[n + 1];
    float ad = g_adst2[n];

    float m = -1e30f, d = 0.f;
    for (int e = beg + lane; e < end; e += 32) {
        int s = g_esrc[e];
        float x = lrelu(g_asrc2[s] + ad);
        g_esc[e] = x;
        float mn = fmaxf(m, x);
        d = d * __expf(m - mn) + __expf(x - mn);
        m = mn;
    }
    #pragma unroll
    for (int o = 16; o; o >>= 1) {
        float mo = __shfl_xor_sync(0xFFFFFFFF, m, o);
        float dd = __shfl_xor_sync(0xFFFFFFFF, d, o);
        float mn = fmaxf(m, mo);
        d = d * __expf(m - mn) + dd * __expf(mo - mn);
        m = mn;
    }
    float inv = 1.f / (d + 1e-16f);
    __syncwarp();

    float2 acc = make_float2(0.f, 0.f);
    int c = lane << 1;
    for (int e0 = beg; e0 < end; e0 += 32) {
        int e = e0 + lane;
        int s = 0; float wt = 0.f;
        if (e < end) {
            s = g_esrc[e];
            wt = __expf(g_esc[e] - m) * inv;
        }
        int cnt = min(32, end - e0);
        for (int j = 0; j < cnt; j++) {
            int   sj = __shfl_sync(0xFFFFFFFF, s, j);
            float wj = __shfl_sync(0xFFFFFFFF, wt, j);
            float2 v = *reinterpret_cast<const float2*>(g_h2 + (size_t)sj * HID + c);
            acc.x += v.x * wj;
            acc.y += v.y * wj;
        }
    }
    float v0 = acc.x + bias[c];
    float v1 = acc.y + bias[c + 1];
    v0 = v0 > 0.f ? v0 : __expf(v0) - 1.f;   // elu
    v1 = v1 > 0.f ? v1 : __expf(v1) - 1.f;

    // MLP layer 1: lane j computes relu(sum_k h[k] * Wm1[k][j] + bm1[j])
    float acc1 = sb1[lane];
    #pragma unroll
    for (int l = 0; l < 32; l++) {
        float b0 = __shfl_sync(0xFFFFFFFF, v0, l);
        float b1 = __shfl_sync(0xFFFFFFFF, v1, l);
        acc1 += b0 * sW1[(2 * l) * 32 + lane] + b1 * sW1[(2 * l + 1) * 32 + lane];
    }
    acc1 = fmaxf(acc1, 0.f);

    // MLP layer 2: out[n][q] = sum_j acc1_j * Wm2[j][q] + bm2[q]
    float p0 = acc1 * sW2[lane * 2];
    float p1 = acc1 * sW2[lane * 2 + 1];
    #pragma unroll
    for (int o = 16; o; o >>= 1) {
        p0 += __shfl_down_sync(0xFFFFFFFF, p0, o);
        p1 += __shfl_down_sync(0xFFFFFFFF, p1, o);
    }
    if (lane == 0) {
        out[n * 2]     = p0 + sb2v[0];
        out[n * 2 + 1] = p1 + sb2v[1];
    }
}

// ---------------- launch ----------------------------------------------------
extern "C" void kernel_launch(void* const* d_in, const int* in_sizes, int n_in,
                              void* d_out, int out_size) {
    const float* x        = (const float*)d_in[0];
    const int*   eidx     = (const int*)d_in[1];
    const float* W1       = (const float*)d_in[2];
    const float* att_src1 = (const float*)d_in[3];
    const float* att_dst1 = (const float*)d_in[4];
    const float* b1       = (const float*)d_in[5];
    const float* W2       = (const float*)d_in[6];
    const float* att_src2 = (const float*)d_in[7];
    const float* att_dst2 = (const float*)d_in[8];
    const float* b2       = (const float*)d_in[9];
    const float* Wm1      = (const float*)d_in[10];
    const float* bm1      = (const float*)d_in[11];
    const float* Wm2      = (const float*)d_in[12];
    const float* bm2      = (const float*)d_in[13];
    float* out = (float*)d_out;

    int E = in_sizes[1] / 2;
    const int* srcp = eidx;
    const int* dstp = eidx + E;

    float *h1p, *h2p, *as1p, *ad1p, *as2p, *ad2p;
    __nv_bfloat16 *a1p, *a2p, *w1p, *w2p;
    cudaGetSymbolAddress((void**)&h1p, g_h1);
    cudaGetSymbolAddress((void**)&h2p, g_h2);
    cudaGetSymbolAddress((void**)&a1p, g_A1);
    cudaGetSymbolAddress((void**)&a2p, g_A2);
    cudaGetSymbolAddress((void**)&w1p, g_W1p);
    cudaGetSymbolAddress((void**)&w2p, g_W2p);
    cudaGetSymbolAddress((void**)&as1p, g_asrc1);
    cudaGetSymbolAddress((void**)&ad1p, g_adst1);
    cudaGetSymbolAddress((void**)&as2p, g_asrc2);
    cudaGetSymbolAddress((void**)&ad2p, g_adst2);

    // dynamic smem: 3 stages * (16KB A + BN*128B B)
    const int SMEM1 = 3 * (16384 + 128 * 128);  // 96KB
    const int SMEM2 = 3 * (16384 + 64 * 128);   // 72KB
    cudaFuncSetAttribute(k_gemm_bf16<128, 2, 4, 4, 2>,
                         cudaFuncAttributeMaxDynamicSharedMemorySize, SMEM1);
    cudaFuncSetAttribute(k_gemm_bf16<64, 4, 2, 2, 1>,
                         cudaFuncAttributeMaxDynamicSharedMemorySize, SMEM2);

    // side stream + events, created once (no destroys mid-capture)
    static cudaStream_t s2 = nullptr;
    static cudaEvent_t evFork = nullptr, evJoin = nullptr;
    if (!s2) {
        cudaStreamCreateWithFlags(&s2, cudaStreamNonBlocking);
        cudaEventCreateWithFlags(&evFork, cudaEventDisableTiming);
        cudaEventCreateWithFlags(&evJoin, cudaEventDisableTiming);
    }

    // fork: CSR build + W2 pack on s2, concurrent with pack/GEMM1
    cudaEventRecord(evFork, 0);
    cudaStreamWaitEvent(s2, evFork, 0);

    k_zero_deg<<<(NN + 255) / 256, 256, 0, s2>>>();
    k_count<<<(E + 255) / 256, 256, 0, s2>>>(dstp, E);
    k_scan1<<<NBLK, 1024, 0, s2>>>();
    k_scan2<<<1, 32, 0, s2>>>();
    k_scan3<<<(NN + 255) / 256, 256, 0, s2>>>();
    k_scatter<<<(E + NN + 255) / 256, 256, 0, s2>>>(srcp, dstp, E);
    k_packW<<<(D1 * HID + 255) / 256, 256, 0, s2>>>(W2, w2p, D1, HID);
    cudaEventRecord(evJoin, s2);

    // main path: pack + GEMM1 (with fused scores1)
    k_packA1<<<(NN * (IN_CH / 2) + 255) / 256, 256>>>(x);
    k_packW<<<(IN_CH * D1 + 255) / 256, 256>>>(W1, w1p, IN_CH, D1);
    k_gemm_bf16<128, 2, 4, 4, 2><<<dim3(D1 / 128, (NN + 127) / 128), 256, SMEM1>>>(
        a1p, w1p, h1p, NN, D1, KP1, att_src1, att_dst1, as1p, ad1p, HEADS);

    // join: agg1 needs CSR; GEMM2 needs W2 pack
    cudaStreamWaitEvent(0, evJoin, 0);
    k_agg1<<<NN, 128>>>(b1);

    // layer 2 GEMM (with fused scores2) + aggregation + MLP head
    k_gemm_bf16<64, 4, 2, 2, 1><<<dim3(HID / 64, (NN + 127) / 128), 256, SMEM2>>>(
        a2p, w2p, h2p, NN, HID, KP2, att_src2, att_dst2, as2p, ad2p, 1);
    k_agg2_mlp<<<(NN + 7) / 8, 256>>>(b2, Wm1, bm1, Wm2, bm2, out);
}